// round 1
// baseline (speedup 1.0000x reference)
#include <cuda_runtime.h>
#include <math.h>

// Problem constants
#define VOCAB 50257
#define DMODEL 128
#define HID 256
#define BATCH 16
#define SEQ 128
#define GATES (3*HID)      // 768
#define MTOK (BATCH*SEQ)   // 2048

// Scratch (allocation-free rule: __device__ globals)
__device__ float g_gx[MTOK * GATES];   // input-side gate projections [2048,768]
__device__ float g_hs[MTOK * HID];     // GRU hidden states          [2048,256]

// ---------------------------------------------------------------------------
// Tiled TN SGEMM: C[M,N] = A'[M,K] * Bm[N,K]^T (+ bias[n])
//   A' row m = A[idx[m]] if HAS_IDX else A[m]   (embedding gather)
// BM=BN=128, BK=16, 256 threads, 8x8 per thread, global->reg prefetch.
// ---------------------------------------------------------------------------
template<bool HAS_IDX, bool HAS_BIAS>
__global__ __launch_bounds__(256)
void gemm_tn(const float* __restrict__ A, const int* __restrict__ idx,
             const float* __restrict__ Bm, const float* __restrict__ bias,
             float* __restrict__ C, int M, int N, int K)
{
    constexpr int BM = 128, BN = 128, BK = 16;
    __shared__ float As[BK][BM];
    __shared__ float Bs[BK][BN];

    const int tid = threadIdx.x;
    const int tx = tid & 15, ty = tid >> 4;
    const int m0 = blockIdx.y * BM, n0 = blockIdx.x * BN;

    // Per-thread load assignments: 2 float4 of A, 2 of B per K-tile.
    int a_row[2], a_col[2], b_row[2], b_col[2];
    const float* a_src[2];
    const float* b_src[2];
    bool b_ok[2];
#pragma unroll
    for (int i = 0; i < 2; i++) {
        int f = tid * 2 + i;
        int r = f >> 2, cv = (f & 3) * 4;
        a_row[i] = r; a_col[i] = cv;
        b_row[i] = r; b_col[i] = cv;
        int gm = m0 + r;
        int src_row = HAS_IDX ? idx[gm] : gm;
        a_src[i] = A + (size_t)src_row * K + cv;
        int gn = n0 + r;
        b_ok[i]  = (gn < N);
        b_src[i] = Bm + (size_t)(b_ok[i] ? gn : 0) * K + cv;
    }

    float acc[8][8];
#pragma unroll
    for (int i = 0; i < 8; i++)
#pragma unroll
        for (int j = 0; j < 8; j++) acc[i][j] = 0.f;

    const int ntiles = K / BK;
    float4 a_reg[2], b_reg[2];
#pragma unroll
    for (int i = 0; i < 2; i++) {
        a_reg[i] = *(const float4*)(a_src[i]);
        b_reg[i] = b_ok[i] ? *(const float4*)(b_src[i]) : make_float4(0.f,0.f,0.f,0.f);
    }

    for (int kt = 0; kt < ntiles; kt++) {
#pragma unroll
        for (int i = 0; i < 2; i++) {
            As[a_col[i]+0][a_row[i]] = a_reg[i].x;
            As[a_col[i]+1][a_row[i]] = a_reg[i].y;
            As[a_col[i]+2][a_row[i]] = a_reg[i].z;
            As[a_col[i]+3][a_row[i]] = a_reg[i].w;
            Bs[b_col[i]+0][b_row[i]] = b_reg[i].x;
            Bs[b_col[i]+1][b_row[i]] = b_reg[i].y;
            Bs[b_col[i]+2][b_row[i]] = b_reg[i].z;
            Bs[b_col[i]+3][b_row[i]] = b_reg[i].w;
        }
        __syncthreads();

        if (kt + 1 < ntiles) {
            int koff = (kt + 1) * BK;
#pragma unroll
            for (int i = 0; i < 2; i++) {
                a_reg[i] = *(const float4*)(a_src[i] + koff);
                b_reg[i] = b_ok[i] ? *(const float4*)(b_src[i] + koff)
                                   : make_float4(0.f,0.f,0.f,0.f);
            }
        }

#pragma unroll
        for (int k = 0; k < BK; k++) {
            float4 a0 = *(const float4*)&As[k][ty * 8];
            float4 a1 = *(const float4*)&As[k][ty * 8 + 4];
            float4 b0 = *(const float4*)&Bs[k][tx * 8];
            float4 b1 = *(const float4*)&Bs[k][tx * 8 + 4];
            float av[8] = {a0.x,a0.y,a0.z,a0.w,a1.x,a1.y,a1.z,a1.w};
            float bv[8] = {b0.x,b0.y,b0.z,b0.w,b1.x,b1.y,b1.z,b1.w};
#pragma unroll
            for (int i = 0; i < 8; i++)
#pragma unroll
                for (int j = 0; j < 8; j++)
                    acc[i][j] += av[i] * bv[j];
        }
        __syncthreads();
    }

#pragma unroll
    for (int i = 0; i < 8; i++) {
        int gm = m0 + ty * 8 + i;
        float* crow = C + (size_t)gm * N + n0 + tx * 8;
#pragma unroll
        for (int j = 0; j < 8; j++) {
            int gn = n0 + tx * 8 + j;
            if (gn < N) {
                float v = acc[i][j];
                if (HAS_BIAS) v += bias[gn];
                crow[j] = v;
            }
        }
    }
}

// ---------------------------------------------------------------------------
// GRU sequential scan. One CTA per batch element, 768 threads (one per gate
// row). h and gh live in smem; W_hh (786 KB) streamed from L2 each step.
// ---------------------------------------------------------------------------
__global__ __launch_bounds__(GATES)
void gru_scan(const float* __restrict__ gx, const float* __restrict__ Whh,
              const float* __restrict__ bhh, float* __restrict__ hs)
{
    __shared__ float h_sm[HID];
    __shared__ float gh_sm[GATES];

    const int b = blockIdx.x;
    const int g = threadIdx.x;   // 0..767

    if (g < HID) h_sm[g] = 0.f;
    __syncthreads();

    const float4* w4 = (const float4*)(Whh + (size_t)g * HID);
    const float bh = bhh[g];

    for (int t = 0; t < SEQ; t++) {
        // gh[g] = b_hh[g] + dot(W_hh[g,:], h)
        const float4* h4 = (const float4*)h_sm;
        float acc = bh;
#pragma unroll 16
        for (int k = 0; k < HID / 4; k++) {
            float4 w = w4[k];
            float4 hv = h4[k];
            acc += w.x * hv.x + w.y * hv.y + w.z * hv.z + w.w * hv.w;
        }
        gh_sm[g] = acc;
        __syncthreads();

        float hnew = 0.f;
        if (g < HID) {
            const float* gxr = gx + (size_t)(b * SEQ + t) * GATES;
            float xr = gxr[g], xz = gxr[HID + g], xn = gxr[2 * HID + g];
            float hr = gh_sm[g], hz = gh_sm[HID + g], hn = gh_sm[2 * HID + g];
            float r = 1.f / (1.f + expf(-(xr + hr)));
            float z = 1.f / (1.f + expf(-(xz + hz)));
            float n = tanhf(xn + r * hn);          // r gates hidden projection
            hnew = (1.f - z) * n + z * h_sm[g];
        }
        __syncthreads();
        if (g < HID) {
            h_sm[g] = hnew;
            hs[(size_t)(b * SEQ + t) * HID + g] = hnew;
        }
        __syncthreads();
    }
}

// ---------------------------------------------------------------------------
// Launch
// ---------------------------------------------------------------------------
extern "C" void kernel_launch(void* const* d_in, const int* in_sizes, int n_in,
                              void* d_out, int out_size)
{
    const int*   ids   = (const int*)  d_in[0];
    const float* embed = (const float*)d_in[1];
    const float* W_ih  = (const float*)d_in[2];
    const float* b_ih  = (const float*)d_in[3];
    const float* W_hh  = (const float*)d_in[4];
    const float* b_hh  = (const float*)d_in[5];
    const float* W_out = (const float*)d_in[6];
    float* out = (float*)d_out;

    float *gx_ptr, *hs_ptr;
    cudaGetSymbolAddress((void**)&gx_ptr, g_gx);
    cudaGetSymbolAddress((void**)&hs_ptr, g_hs);

    // 1) gx = embed[ids] @ W_ih^T + b_ih   (M=2048, N=768, K=128)
    {
        dim3 grid(GATES / 128, MTOK / 128);
        gemm_tn<true, true><<<grid, 256>>>(embed, ids, W_ih, b_ih,
                                           gx_ptr, MTOK, GATES, DMODEL);
    }

    // 2) GRU scan over T=128 steps
    gru_scan<<<BATCH, GATES>>>(gx_ptr, W_hh, b_hh, hs_ptr);

    // 3) LM head: out = hs @ W_out^T   (M=2048, N=50257, K=256)
    {
        dim3 grid((VOCAB + 127) / 128, MTOK / 128);
        gemm_tn<false, false><<<grid, 256>>>(hs_ptr, nullptr, W_out, nullptr,
                                             out, MTOK, VOCAB, HID);
    }
}

// round 3
// speedup vs baseline: 1.2780x; 1.2780x over previous
#include <cuda_runtime.h>
#include <cuda_bf16.h>
#include <math.h>
#include <stdint.h>

// Problem constants
#define VOCAB 50257
#define NPAD  50304              // 393 * 128
#define DMODEL 128
#define HID 256
#define BATCH 16
#define SEQ 128
#define GATES (3*HID)            // 768
#define MTOK (BATCH*SEQ)         // 2048
#define KCAT 768                 // concatenated K for 3-term split

// Scratch (__device__ globals per allocation-free rule)
__device__ float g_gx[MTOK * GATES];              // input-side gate projections
__device__ __nv_bfloat16 g_a2[MTOK * KCAT];       // [Ah | Ah | Al]
__device__ __nv_bfloat16 g_b2[NPAD * KCAT];       // [Bh | Bl | Bh]

__device__ __forceinline__ uint32_t smem_to_u32(const void* p) {
    uint32_t a;
    asm("{ .reg .u64 t; cvta.to.shared.u64 t, %1; cvt.u32.u64 %0, t; }"
        : "=r"(a) : "l"(p));
    return a;
}

// ---------------------------------------------------------------------------
// Stage 1: tiled TN SGEMM with gather + bias (proven in round 1)
// ---------------------------------------------------------------------------
template<bool HAS_IDX, bool HAS_BIAS>
__global__ __launch_bounds__(256)
void gemm_tn(const float* __restrict__ A, const int* __restrict__ idx,
             const float* __restrict__ Bm, const float* __restrict__ bias,
             float* __restrict__ C, int M, int N, int K)
{
    constexpr int BM = 128, BN = 128, BK = 16;
    __shared__ float As[BK][BM];
    __shared__ float Bs[BK][BN];

    const int tid = threadIdx.x;
    const int tx = tid & 15, ty = tid >> 4;
    const int m0 = blockIdx.y * BM, n0 = blockIdx.x * BN;

    int a_row[2], a_col[2], b_row[2], b_col[2];
    const float* a_src[2];
    const float* b_src[2];
    bool b_ok[2];
#pragma unroll
    for (int i = 0; i < 2; i++) {
        int f = tid * 2 + i;
        int r = f >> 2, cv = (f & 3) * 4;
        a_row[i] = r; a_col[i] = cv;
        b_row[i] = r; b_col[i] = cv;
        int gm = m0 + r;
        int src_row = HAS_IDX ? idx[gm] : gm;
        a_src[i] = A + (size_t)src_row * K + cv;
        int gn = n0 + r;
        b_ok[i]  = (gn < N);
        b_src[i] = Bm + (size_t)(b_ok[i] ? gn : 0) * K + cv;
    }

    float acc[8][8];
#pragma unroll
    for (int i = 0; i < 8; i++)
#pragma unroll
        for (int j = 0; j < 8; j++) acc[i][j] = 0.f;

    const int ntiles = K / BK;
    float4 a_reg[2], b_reg[2];
#pragma unroll
    for (int i = 0; i < 2; i++) {
        a_reg[i] = *(const float4*)(a_src[i]);
        b_reg[i] = b_ok[i] ? *(const float4*)(b_src[i]) : make_float4(0.f,0.f,0.f,0.f);
    }

    for (int kt = 0; kt < ntiles; kt++) {
#pragma unroll
        for (int i = 0; i < 2; i++) {
            As[a_col[i]+0][a_row[i]] = a_reg[i].x;
            As[a_col[i]+1][a_row[i]] = a_reg[i].y;
            As[a_col[i]+2][a_row[i]] = a_reg[i].z;
            As[a_col[i]+3][a_row[i]] = a_reg[i].w;
            Bs[b_col[i]+0][b_row[i]] = b_reg[i].x;
            Bs[b_col[i]+1][b_row[i]] = b_reg[i].y;
            Bs[b_col[i]+2][b_row[i]] = b_reg[i].z;
            Bs[b_col[i]+3][b_row[i]] = b_reg[i].w;
        }
        __syncthreads();

        if (kt + 1 < ntiles) {
            int koff = (kt + 1) * BK;
#pragma unroll
            for (int i = 0; i < 2; i++) {
                a_reg[i] = *(const float4*)(a_src[i] + koff);
                b_reg[i] = b_ok[i] ? *(const float4*)(b_src[i] + koff)
                                   : make_float4(0.f,0.f,0.f,0.f);
            }
        }

#pragma unroll
        for (int k = 0; k < BK; k++) {
            float4 a0 = *(const float4*)&As[k][ty * 8];
            float4 a1 = *(const float4*)&As[k][ty * 8 + 4];
            float4 b0 = *(const float4*)&Bs[k][tx * 8];
            float4 b1 = *(const float4*)&Bs[k][tx * 8 + 4];
            float av[8] = {a0.x,a0.y,a0.z,a0.w,a1.x,a1.y,a1.z,a1.w};
            float bv[8] = {b0.x,b0.y,b0.z,b0.w,b1.x,b1.y,b1.z,b1.w};
#pragma unroll
            for (int i = 0; i < 8; i++)
#pragma unroll
                for (int j = 0; j < 8; j++)
                    acc[i][j] += av[i] * bv[j];
        }
        __syncthreads();
    }

#pragma unroll
    for (int i = 0; i < 8; i++) {
        int gm = m0 + ty * 8 + i;
        float* crow = C + (size_t)gm * N + n0 + tx * 8;
#pragma unroll
        for (int j = 0; j < 8; j++) {
            int gn = n0 + tx * 8 + j;
            if (gn < N) {
                float v = acc[i][j];
                if (HAS_BIAS) v += bias[gn];
                crow[j] = v;
            }
        }
    }
}

// ---------------------------------------------------------------------------
// Stage 2: GRU scan; emits A2 = [hi | hi | lo] bf16 rows directly.
// ---------------------------------------------------------------------------
__global__ __launch_bounds__(GATES)
void gru_scan(const float* __restrict__ gx, const float* __restrict__ Whh,
              const float* __restrict__ bhh, __nv_bfloat16* __restrict__ a2)
{
    __shared__ float h_sm[HID];
    __shared__ float gh_sm[GATES];

    const int b = blockIdx.x;
    const int g = threadIdx.x;

    if (g < HID) h_sm[g] = 0.f;
    __syncthreads();

    const float4* w4 = (const float4*)(Whh + (size_t)g * HID);
    const float bh = bhh[g];

    for (int t = 0; t < SEQ; t++) {
        const float4* h4 = (const float4*)h_sm;
        float acc = bh;
#pragma unroll 16
        for (int k = 0; k < HID / 4; k++) {
            float4 w = w4[k];
            float4 hv = h4[k];
            acc += w.x * hv.x + w.y * hv.y + w.z * hv.z + w.w * hv.w;
        }
        gh_sm[g] = acc;
        __syncthreads();

        float hnew = 0.f;
        if (g < HID) {
            const float* gxr = gx + (size_t)(b * SEQ + t) * GATES;
            float xr = gxr[g], xz = gxr[HID + g], xn = gxr[2 * HID + g];
            float hr = gh_sm[g], hz = gh_sm[HID + g], hn = gh_sm[2 * HID + g];
            float r = 1.f / (1.f + expf(-(xr + hr)));
            float z = 1.f / (1.f + expf(-(xz + hz)));
            float n = tanhf(xn + r * hn);
            hnew = (1.f - z) * n + z * h_sm[g];
        }
        __syncthreads();
        if (g < HID) {
            h_sm[g] = hnew;
            size_t base = (size_t)(b * SEQ + t) * KCAT;
            __nv_bfloat16 hh = __float2bfloat16_rn(hnew);
            __nv_bfloat16 hl = __float2bfloat16_rn(hnew - __bfloat162float(hh));
            a2[base + g]            = hh;
            a2[base + HID + g]      = hh;
            a2[base + 2 * HID + g]  = hl;
        }
        __syncthreads();
    }
}

// ---------------------------------------------------------------------------
// W_out -> B2 = [hi | lo | hi] bf16 rows (padded/zeroed to NPAD rows)
// ---------------------------------------------------------------------------
__global__ __launch_bounds__(256)
void conv_w2(const float* __restrict__ W, __nv_bfloat16* __restrict__ B2)
{
    int idx = blockIdx.x * blockDim.x + threadIdx.x;   // one per 4 k-elems
    int v = idx >> 6;
    int k4 = (idx & 63) * 4;
    if (v >= NPAD) return;

    __nv_bfloat162 h01, h23, l01, l23;
    if (v < VOCAB) {
        float4 x = *(const float4*)(W + (size_t)v * HID + k4);
        __nv_bfloat16 h0 = __float2bfloat16_rn(x.x);
        __nv_bfloat16 h1 = __float2bfloat16_rn(x.y);
        __nv_bfloat16 h2 = __float2bfloat16_rn(x.z);
        __nv_bfloat16 h3 = __float2bfloat16_rn(x.w);
        h01 = __halves2bfloat162(h0, h1);
        h23 = __halves2bfloat162(h2, h3);
        l01 = __halves2bfloat162(__float2bfloat16_rn(x.x - __bfloat162float(h0)),
                                 __float2bfloat16_rn(x.y - __bfloat162float(h1)));
        l23 = __halves2bfloat162(__float2bfloat16_rn(x.z - __bfloat162float(h2)),
                                 __float2bfloat16_rn(x.w - __bfloat162float(h3)));
    } else {
        h01 = h23 = l01 = l23 = __halves2bfloat162(__float2bfloat16_rn(0.f),
                                                   __float2bfloat16_rn(0.f));
    }
    __nv_bfloat162* row = (__nv_bfloat162*)(B2 + (size_t)v * KCAT);
    row[(k4 >> 1)]                 = h01;  row[(k4 >> 1) + 1]                 = h23;
    row[(HID + k4) >> 1]           = l01;  row[((HID + k4) >> 1) + 1]         = l23;
    row[(2 * HID + k4) >> 1]       = h01;  row[((2 * HID + k4) >> 1) + 1]     = h23;
}

// ---------------------------------------------------------------------------
// Stage 3: LM head via mma.sync (HMMA) bf16, K=768 concatenated.
// CTA tile 128x128, 8 warps (2x4), warp tile 64x32, BK=64, cp.async 2-stage.
// ---------------------------------------------------------------------------
#define LM_BK 64
#define LM_NT (KCAT / LM_BK)          // 12
#define LM_TILE_B 16384               // 128 rows * 128 bytes
#define LM_STAGE_B (2 * LM_TILE_B)    // A + B per stage
#define LM_SMEM (2 * LM_STAGE_B)      // 65536

__device__ __forceinline__ void cp16(uint32_t saddr, const void* gaddr) {
    asm volatile("cp.async.cg.shared.global [%0], [%1], 16;"
                 :: "r"(saddr), "l"(gaddr));
}

__global__ __launch_bounds__(256, 1)
void lm_head_hmma(const __nv_bfloat16* __restrict__ A2,
                  const __nv_bfloat16* __restrict__ B2,
                  float* __restrict__ out)
{
    extern __shared__ char smem[];
    const uint32_t sbase = smem_to_u32(smem);

    const int tid = threadIdx.x;
    const int lane = tid & 31;
    const int wid = tid >> 5;
    const int m0 = blockIdx.x * 128;
    const int n0 = blockIdx.y * 128;
    const int wm = (wid >> 2) * 64;   // warp M offset (2 warps)
    const int wn = (wid & 3) * 32;    // warp N offset (4 warps)

    // ldmatrix lane constants
    const int lg = lane >> 3, lr = lane & 7;
    const int row16 = ((lg & 1) << 3) + lr;   // row within 16-row block
    const int csel  = lg >> 1;                // k-chunk select (16B units)

    float acc[4][4][4];
#pragma unroll
    for (int i = 0; i < 4; i++)
#pragma unroll
        for (int j = 0; j < 4; j++)
#pragma unroll
            for (int k = 0; k < 4; k++) acc[i][j][k] = 0.f;

    // --- cp.async tile loader: 1024 x 16B chunks per matrix, 4 per thread ---
    auto issue = [&](int kt) {
        const uint32_t stage = sbase + (kt & 1) * LM_STAGE_B;
#pragma unroll
        for (int i = 0; i < 4; i++) {
            int q = i * 256 + tid;
            int row = q >> 3, c = q & 7;
            uint32_t soff = row * 128 + (((uint32_t)(c ^ (row & 7))) << 4);
            cp16(stage + soff,
                 A2 + (size_t)(m0 + row) * KCAT + kt * LM_BK + c * 8);
            cp16(stage + LM_TILE_B + soff,
                 B2 + (size_t)(n0 + row) * KCAT + kt * LM_BK + c * 8);
        }
        asm volatile("cp.async.commit_group;" ::: "memory");
    };

    issue(0);

    for (int kt = 0; kt < LM_NT; kt++) {
        if (kt + 1 < LM_NT) {
            issue(kt + 1);
            asm volatile("cp.async.wait_group 1;" ::: "memory");
        } else {
            asm volatile("cp.async.wait_group 0;" ::: "memory");
        }
        __syncthreads();

        const uint32_t Ab = sbase + (kt & 1) * LM_STAGE_B;
        const uint32_t Bb = Ab + LM_TILE_B;

#pragma unroll
        for (int ks = 0; ks < 4; ks++) {
            const int kc = ks * 2;
            uint32_t a[4][4];
#pragma unroll
            for (int mt = 0; mt < 4; mt++) {
                int row = wm + mt * 16 + row16;
                uint32_t addr = Ab + row * 128 +
                    (((uint32_t)((kc + csel) ^ (row & 7))) << 4);
                asm volatile(
                    "ldmatrix.sync.aligned.m8n8.x4.shared.b16 {%0,%1,%2,%3}, [%4];"
                    : "=r"(a[mt][0]), "=r"(a[mt][1]), "=r"(a[mt][2]), "=r"(a[mt][3])
                    : "r"(addr));
            }
            uint32_t bf[4][2];
#pragma unroll
            for (int np = 0; np < 2; np++) {
                int row = wn + np * 16 + row16;
                uint32_t addr = Bb + row * 128 +
                    (((uint32_t)((kc + csel) ^ (row & 7))) << 4);
                uint32_t q0, q1, q2, q3;
                asm volatile(
                    "ldmatrix.sync.aligned.m8n8.x4.shared.b16 {%0,%1,%2,%3}, [%4];"
                    : "=r"(q0), "=r"(q1), "=r"(q2), "=r"(q3)
                    : "r"(addr));
                bf[np * 2][0] = q0;     bf[np * 2][1] = q2;
                bf[np * 2 + 1][0] = q1; bf[np * 2 + 1][1] = q3;
            }
#pragma unroll
            for (int mt = 0; mt < 4; mt++)
#pragma unroll
                for (int nt = 0; nt < 4; nt++) {
                    asm volatile(
                        "mma.sync.aligned.m16n8k16.row.col.f32.bf16.bf16.f32 "
                        "{%0,%1,%2,%3}, {%4,%5,%6,%7}, {%8,%9}, {%0,%1,%2,%3};"
                        : "+f"(acc[mt][nt][0]), "+f"(acc[mt][nt][1]),
                          "+f"(acc[mt][nt][2]), "+f"(acc[mt][nt][3])
                        : "r"(a[mt][0]), "r"(a[mt][1]), "r"(a[mt][2]), "r"(a[mt][3]),
                          "r"(bf[nt][0]), "r"(bf[nt][1]));
                }
        }
        __syncthreads();
    }

    // --- Epilogue: direct fragment stores (4-lane groups fill 32B sectors) ---
    const int elr = lane >> 2;
    const int elc = (lane & 3) * 2;
    const bool full = (n0 + 128 <= VOCAB);
#pragma unroll
    for (int mt = 0; mt < 4; mt++) {
#pragma unroll
        for (int nt = 0; nt < 4; nt++) {
            int gr = m0 + wm + mt * 16 + elr;
            int gc = n0 + wn + nt * 8 + elc;
            float* p0 = out + (size_t)gr * VOCAB + gc;
            float* p1 = out + (size_t)(gr + 8) * VOCAB + gc;
            if (full) {
                p0[0] = acc[mt][nt][0]; p0[1] = acc[mt][nt][1];
                p1[0] = acc[mt][nt][2]; p1[1] = acc[mt][nt][3];
            } else {
                if (gc < VOCAB)     { p0[0] = acc[mt][nt][0]; p1[0] = acc[mt][nt][2]; }
                if (gc + 1 < VOCAB) { p0[1] = acc[mt][nt][1]; p1[1] = acc[mt][nt][3]; }
            }
        }
    }
}

// ---------------------------------------------------------------------------
// Launch
// ---------------------------------------------------------------------------
extern "C" void kernel_launch(void* const* d_in, const int* in_sizes, int n_in,
                              void* d_out, int out_size)
{
    const int*   ids   = (const int*)  d_in[0];
    const float* embed = (const float*)d_in[1];
    const float* W_ih  = (const float*)d_in[2];
    const float* b_ih  = (const float*)d_in[3];
    const float* W_hh  = (const float*)d_in[4];
    const float* b_hh  = (const float*)d_in[5];
    const float* W_out = (const float*)d_in[6];
    float* out = (float*)d_out;

    float* gx_ptr;
    __nv_bfloat16 *a2_ptr, *b2_ptr;
    cudaGetSymbolAddress((void**)&gx_ptr, g_gx);
    cudaGetSymbolAddress((void**)&a2_ptr, g_a2);
    cudaGetSymbolAddress((void**)&b2_ptr, g_b2);

    cudaFuncSetAttribute(lm_head_hmma,
                         cudaFuncAttributeMaxDynamicSharedMemorySize, LM_SMEM);

    // 0) B2 = [hi | lo | hi] split of W_out
    {
        int nthreads = NPAD * 64;
        conv_w2<<<(nthreads + 255) / 256, 256>>>(W_out, b2_ptr);
    }

    // 1) gx = embed[ids] @ W_ih^T + b_ih
    {
        dim3 grid(GATES / 128, MTOK / 128);
        gemm_tn<true, true><<<grid, 256>>>(embed, ids, W_ih, b_ih,
                                           gx_ptr, MTOK, GATES, DMODEL);
    }

    // 2) GRU scan (emits A2 rows)
    gru_scan<<<BATCH, GATES>>>(gx_ptr, W_hh, b_hh, a2_ptr);

    // 3) LM head on HMMA tensor cores
    {
        dim3 grid(MTOK / 128, NPAD / 128);
        lm_head_hmma<<<grid, 256, LM_SMEM>>>(a2_ptr, b2_ptr, out);
    }
}

// round 4
// speedup vs baseline: 4.1575x; 3.2530x over previous
#include <cuda_runtime.h>
#include <cuda_bf16.h>
#include <math.h>
#include <stdint.h>

// Problem constants
#define VOCAB 50257
#define NPAD  50304              // 393 * 128
#define DMODEL 128
#define HID 256
#define BATCH 16
#define SEQ 128
#define GATES (3*HID)            // 768
#define MTOK (BATCH*SEQ)         // 2048
#define KCAT 768                 // concatenated K for 3-term split

// Scratch (__device__ globals per allocation-free rule)
__device__ float g_gx[MTOK * GATES];              // input-side gate projections
__device__ __nv_bfloat16 g_a2[MTOK * KCAT];       // [Ah | Ah | Al]
__device__ __nv_bfloat16 g_b2[NPAD * KCAT];       // [Bh | Bl | Bh]
__device__ unsigned int g_bar;                    // inter-CTA barrier counter
__device__ float g_hbuf[2][HID * BATCH];          // double-buffered h exchange

__device__ __forceinline__ uint32_t smem_to_u32(const void* p) {
    uint32_t a;
    asm("{ .reg .u64 t; cvta.to.shared.u64 t, %1; cvt.u32.u64 %0, t; }"
        : "=r"(a) : "l"(p));
    return a;
}

// ---------------------------------------------------------------------------
// Stage 1: tiled TN SGEMM with gather + bias (proven)
// ---------------------------------------------------------------------------
template<bool HAS_IDX, bool HAS_BIAS>
__global__ __launch_bounds__(256)
void gemm_tn(const float* __restrict__ A, const int* __restrict__ idx,
             const float* __restrict__ Bm, const float* __restrict__ bias,
             float* __restrict__ C, int M, int N, int K)
{
    constexpr int BM = 128, BN = 128, BK = 16;
    __shared__ float As[BK][BM];
    __shared__ float Bs[BK][BN];

    const int tid = threadIdx.x;
    const int tx = tid & 15, ty = tid >> 4;
    const int m0 = blockIdx.y * BM, n0 = blockIdx.x * BN;

    int a_row[2], a_col[2], b_row[2], b_col[2];
    const float* a_src[2];
    const float* b_src[2];
    bool b_ok[2];
#pragma unroll
    for (int i = 0; i < 2; i++) {
        int f = tid * 2 + i;
        int r = f >> 2, cv = (f & 3) * 4;
        a_row[i] = r; a_col[i] = cv;
        b_row[i] = r; b_col[i] = cv;
        int gm = m0 + r;
        int src_row = HAS_IDX ? idx[gm] : gm;
        a_src[i] = A + (size_t)src_row * K + cv;
        int gn = n0 + r;
        b_ok[i]  = (gn < N);
        b_src[i] = Bm + (size_t)(b_ok[i] ? gn : 0) * K + cv;
    }

    float acc[8][8];
#pragma unroll
    for (int i = 0; i < 8; i++)
#pragma unroll
        for (int j = 0; j < 8; j++) acc[i][j] = 0.f;

    const int ntiles = K / BK;
    float4 a_reg[2], b_reg[2];
#pragma unroll
    for (int i = 0; i < 2; i++) {
        a_reg[i] = *(const float4*)(a_src[i]);
        b_reg[i] = b_ok[i] ? *(const float4*)(b_src[i]) : make_float4(0.f,0.f,0.f,0.f);
    }

    for (int kt = 0; kt < ntiles; kt++) {
#pragma unroll
        for (int i = 0; i < 2; i++) {
            As[a_col[i]+0][a_row[i]] = a_reg[i].x;
            As[a_col[i]+1][a_row[i]] = a_reg[i].y;
            As[a_col[i]+2][a_row[i]] = a_reg[i].z;
            As[a_col[i]+3][a_row[i]] = a_reg[i].w;
            Bs[b_col[i]+0][b_row[i]] = b_reg[i].x;
            Bs[b_col[i]+1][b_row[i]] = b_reg[i].y;
            Bs[b_col[i]+2][b_row[i]] = b_reg[i].z;
            Bs[b_col[i]+3][b_row[i]] = b_reg[i].w;
        }
        __syncthreads();

        if (kt + 1 < ntiles) {
            int koff = (kt + 1) * BK;
#pragma unroll
            for (int i = 0; i < 2; i++) {
                a_reg[i] = *(const float4*)(a_src[i] + koff);
                b_reg[i] = b_ok[i] ? *(const float4*)(b_src[i] + koff)
                                   : make_float4(0.f,0.f,0.f,0.f);
            }
        }

#pragma unroll
        for (int k = 0; k < BK; k++) {
            float4 a0 = *(const float4*)&As[k][ty * 8];
            float4 a1 = *(const float4*)&As[k][ty * 8 + 4];
            float4 b0 = *(const float4*)&Bs[k][tx * 8];
            float4 b1 = *(const float4*)&Bs[k][tx * 8 + 4];
            float av[8] = {a0.x,a0.y,a0.z,a0.w,a1.x,a1.y,a1.z,a1.w};
            float bv[8] = {b0.x,b0.y,b0.z,b0.w,b1.x,b1.y,b1.z,b1.w};
#pragma unroll
            for (int i = 0; i < 8; i++)
#pragma unroll
                for (int j = 0; j < 8; j++)
                    acc[i][j] += av[i] * bv[j];
        }
        __syncthreads();
    }

#pragma unroll
    for (int i = 0; i < 8; i++) {
        int gm = m0 + ty * 8 + i;
        float* crow = C + (size_t)gm * N + n0 + tx * 8;
#pragma unroll
        for (int j = 0; j < 8; j++) {
            int gn = n0 + tx * 8 + j;
            if (gn < N) {
                float v = acc[i][j];
                if (HAS_BIAS) v += bias[gn];
                crow[j] = v;
            }
        }
    }
}

// ---------------------------------------------------------------------------
// Stage 2: multi-CTA GRU scan. 32 CTAs; CTA c owns hidden units [8c, 8c+8)
// (its 24 W_hh rows live in SMEM). One gpu-scope barrier per timestep.
// ---------------------------------------------------------------------------
#define NC 32
#define UPC 8                    // units per CTA
#define RPC 24                   // W rows per CTA (r,z,n gates of its units)
#define GRU_THREADS 384
#define WPAD 260                 // row stride (floats): 16B-aligned, bank-skewed

__global__ __launch_bounds__(GRU_THREADS)
void gru_scan2(const float* __restrict__ gx, const float* __restrict__ Whh,
               const float* __restrict__ bhh, __nv_bfloat16* __restrict__ a2)
{
    __shared__ float W_sm[RPC][WPAD];
    __shared__ float H_sm[HID * BATCH];     // [unit][batch]
    __shared__ float gh_sm[RPC][BATCH];

    const int cta = blockIdx.x;
    const int tid = threadIdx.x;
    const int rl  = tid >> 4;               // 0..23  local gate-row
    const int b   = tid & 15;               // batch

    // Map local row -> global W_hh row (r gates, then z, then n, own units)
    auto grow_of = [&](int r) {
        return (r < UPC)     ? cta * UPC + r
             : (r < 2*UPC)   ? HID + cta * UPC + (r - UPC)
                             : 2 * HID + cta * UPC + (r - 2*UPC);
    };

    for (int i = tid; i < RPC * HID; i += GRU_THREADS) {
        int r = i / HID, k = i % HID;
        W_sm[r][k] = Whh[(size_t)grow_of(r) * HID + k];
    }
    const float bias = bhh[grow_of(rl)];
    for (int i = tid; i < HID * BATCH; i += GRU_THREADS) H_sm[i] = 0.f;
    __syncthreads();

    const int u   = tid >> 4;               // update-unit index (tid < 128)
    const int uid = cta * UPC + u;          // global unit

    for (int t = 0; t < SEQ; t++) {
        // Prefetch gx operands for h-update (independent of barrier)
        float xr = 0.f, xz = 0.f, xn = 0.f;
        if (tid < UPC * BATCH) {
            const float* gxr = gx + (size_t)(b * SEQ + t) * GATES;
            xr = gxr[uid]; xz = gxr[HID + uid]; xn = gxr[2 * HID + uid];
        }

        // gh[rl][b] = bias + dot(W_sm[rl], H[:,b])  (4 accumulators)
        float s0 = bias, s1 = 0.f, s2 = 0.f, s3 = 0.f;
#pragma unroll 16
        for (int k = 0; k < HID; k += 4) {
            float4 w = *(const float4*)&W_sm[rl][k];
            s0 += w.x * H_sm[(k    ) * BATCH + b];
            s1 += w.y * H_sm[(k + 1) * BATCH + b];
            s2 += w.z * H_sm[(k + 2) * BATCH + b];
            s3 += w.w * H_sm[(k + 3) * BATCH + b];
        }
        gh_sm[rl][b] = (s0 + s1) + (s2 + s3);
        __syncthreads();

        // h-update for own 8 units x 16 batches (threads 0..127)
        if (tid < UPC * BATCH) {
            float hr = gh_sm[u][b];
            float hz = gh_sm[UPC + u][b];
            float hn = gh_sm[2 * UPC + u][b];
            float hp = H_sm[uid * BATCH + b];
            float r = 1.f / (1.f + expf(-(xr + hr)));
            float z = 1.f / (1.f + expf(-(xz + hz)));
            float n = tanhf(xn + r * hn);
            float hnew = (1.f - z) * n + z * hp;
            g_hbuf[t & 1][uid * BATCH + b] = hnew;
            // emit A2 = [hi | hi | lo]
            size_t base = (size_t)(b * SEQ + t) * KCAT;
            __nv_bfloat16 hh = __float2bfloat16_rn(hnew);
            a2[base + uid]           = hh;
            a2[base + HID + uid]     = hh;
            a2[base + 2 * HID + uid] = __float2bfloat16_rn(hnew - __bfloat162float(hh));
        }
        __syncthreads();

        // gpu-scope barrier: all CTAs published h for step t
        if (tid == 0) {
            __threadfence();                       // release own writes
            atomicAdd(&g_bar, 1u);
            const unsigned tgt = (unsigned)NC * (t + 1);
            unsigned v;
            do {
                asm volatile("ld.acquire.gpu.u32 %0, [%1];"
                             : "=r"(v) : "l"(&g_bar) : "memory");
            } while (v < tgt);
        }
        __syncthreads();

        // refresh full H from global exchange buffer
        for (int i = tid; i < HID * BATCH; i += GRU_THREADS)
            H_sm[i] = g_hbuf[t & 1][i];
        __syncthreads();
    }
}

// ---------------------------------------------------------------------------
// W_out -> B2 = [hi | lo | hi] bf16 rows (padded/zeroed to NPAD rows)
// ---------------------------------------------------------------------------
__global__ __launch_bounds__(256)
void conv_w2(const float* __restrict__ W, __nv_bfloat16* __restrict__ B2)
{
    int idx = blockIdx.x * blockDim.x + threadIdx.x;   // one per 4 k-elems
    int v = idx >> 6;
    int k4 = (idx & 63) * 4;
    if (v >= NPAD) return;

    __nv_bfloat162 h01, h23, l01, l23;
    if (v < VOCAB) {
        float4 x = *(const float4*)(W + (size_t)v * HID + k4);
        __nv_bfloat16 h0 = __float2bfloat16_rn(x.x);
        __nv_bfloat16 h1 = __float2bfloat16_rn(x.y);
        __nv_bfloat16 h2 = __float2bfloat16_rn(x.z);
        __nv_bfloat16 h3 = __float2bfloat16_rn(x.w);
        h01 = __halves2bfloat162(h0, h1);
        h23 = __halves2bfloat162(h2, h3);
        l01 = __halves2bfloat162(__float2bfloat16_rn(x.x - __bfloat162float(h0)),
                                 __float2bfloat16_rn(x.y - __bfloat162float(h1)));
        l23 = __halves2bfloat162(__float2bfloat16_rn(x.z - __bfloat162float(h2)),
                                 __float2bfloat16_rn(x.w - __bfloat162float(h3)));
    } else {
        h01 = h23 = l01 = l23 = __halves2bfloat162(__float2bfloat16_rn(0.f),
                                                   __float2bfloat16_rn(0.f));
    }
    __nv_bfloat162* row = (__nv_bfloat162*)(B2 + (size_t)v * KCAT);
    row[(k4 >> 1)]                 = h01;  row[(k4 >> 1) + 1]                 = h23;
    row[(HID + k4) >> 1]           = l01;  row[((HID + k4) >> 1) + 1]         = l23;
    row[(2 * HID + k4) >> 1]       = h01;  row[((2 * HID + k4) >> 1) + 1]     = h23;
}

// ---------------------------------------------------------------------------
// Stage 3: LM head via mma.sync (HMMA) bf16, K=768 concatenated.
// ---------------------------------------------------------------------------
#define LM_BK 64
#define LM_NT (KCAT / LM_BK)          // 12
#define LM_TILE_B 16384               // 128 rows * 128 bytes
#define LM_STAGE_B (2 * LM_TILE_B)
#define LM_SMEM (2 * LM_STAGE_B)      // 65536

__device__ __forceinline__ void cp16(uint32_t saddr, const void* gaddr) {
    asm volatile("cp.async.cg.shared.global [%0], [%1], 16;"
                 :: "r"(saddr), "l"(gaddr));
}

__global__ __launch_bounds__(256, 1)
void lm_head_hmma(const __nv_bfloat16* __restrict__ A2,
                  const __nv_bfloat16* __restrict__ B2,
                  float* __restrict__ out)
{
    extern __shared__ char smem[];
    const uint32_t sbase = smem_to_u32(smem);

    const int tid = threadIdx.x;
    const int lane = tid & 31;
    const int wid = tid >> 5;
    const int m0 = blockIdx.x * 128;
    const int n0 = blockIdx.y * 128;
    const int wm = (wid >> 2) * 64;
    const int wn = (wid & 3) * 32;

    const int lg = lane >> 3, lr = lane & 7;
    const int row16 = ((lg & 1) << 3) + lr;
    const int csel  = lg >> 1;

    float acc[4][4][4];
#pragma unroll
    for (int i = 0; i < 4; i++)
#pragma unroll
        for (int j = 0; j < 4; j++)
#pragma unroll
            for (int k = 0; k < 4; k++) acc[i][j][k] = 0.f;

    auto issue = [&](int kt) {
        const uint32_t stage = sbase + (kt & 1) * LM_STAGE_B;
#pragma unroll
        for (int i = 0; i < 4; i++) {
            int q = i * 256 + tid;
            int row = q >> 3, c = q & 7;
            uint32_t soff = row * 128 + (((uint32_t)(c ^ (row & 7))) << 4);
            cp16(stage + soff,
                 A2 + (size_t)(m0 + row) * KCAT + kt * LM_BK + c * 8);
            cp16(stage + LM_TILE_B + soff,
                 B2 + (size_t)(n0 + row) * KCAT + kt * LM_BK + c * 8);
        }
        asm volatile("cp.async.commit_group;" ::: "memory");
    };

    issue(0);

    for (int kt = 0; kt < LM_NT; kt++) {
        if (kt + 1 < LM_NT) {
            issue(kt + 1);
            asm volatile("cp.async.wait_group 1;" ::: "memory");
        } else {
            asm volatile("cp.async.wait_group 0;" ::: "memory");
        }
        __syncthreads();

        const uint32_t Ab = sbase + (kt & 1) * LM_STAGE_B;
        const uint32_t Bb = Ab + LM_TILE_B;

#pragma unroll
        for (int ks = 0; ks < 4; ks++) {
            const int kc = ks * 2;
            uint32_t a[4][4];
#pragma unroll
            for (int mt = 0; mt < 4; mt++) {
                int row = wm + mt * 16 + row16;
                uint32_t addr = Ab + row * 128 +
                    (((uint32_t)((kc + csel) ^ (row & 7))) << 4);
                asm volatile(
                    "ldmatrix.sync.aligned.m8n8.x4.shared.b16 {%0,%1,%2,%3}, [%4];"
                    : "=r"(a[mt][0]), "=r"(a[mt][1]), "=r"(a[mt][2]), "=r"(a[mt][3])
                    : "r"(addr));
            }
            uint32_t bf[4][2];
#pragma unroll
            for (int np = 0; np < 2; np++) {
                int row = wn + np * 16 + row16;
                uint32_t addr = Bb + row * 128 +
                    (((uint32_t)((kc + csel) ^ (row & 7))) << 4);
                uint32_t q0, q1, q2, q3;
                asm volatile(
                    "ldmatrix.sync.aligned.m8n8.x4.shared.b16 {%0,%1,%2,%3}, [%4];"
                    : "=r"(q0), "=r"(q1), "=r"(q2), "=r"(q3)
                    : "r"(addr));
                bf[np * 2][0] = q0;     bf[np * 2][1] = q2;
                bf[np * 2 + 1][0] = q1; bf[np * 2 + 1][1] = q3;
            }
#pragma unroll
            for (int mt = 0; mt < 4; mt++)
#pragma unroll
                for (int nt = 0; nt < 4; nt++) {
                    asm volatile(
                        "mma.sync.aligned.m16n8k16.row.col.f32.bf16.bf16.f32 "
                        "{%0,%1,%2,%3}, {%4,%5,%6,%7}, {%8,%9}, {%0,%1,%2,%3};"
                        : "+f"(acc[mt][nt][0]), "+f"(acc[mt][nt][1]),
                          "+f"(acc[mt][nt][2]), "+f"(acc[mt][nt][3])
                        : "r"(a[mt][0]), "r"(a[mt][1]), "r"(a[mt][2]), "r"(a[mt][3]),
                          "r"(bf[nt][0]), "r"(bf[nt][1]));
                }
        }
        __syncthreads();
    }

    const int elr = lane >> 2;
    const int elc = (lane & 3) * 2;
    const bool full = (n0 + 128 <= VOCAB);
#pragma unroll
    for (int mt = 0; mt < 4; mt++) {
#pragma unroll
        for (int nt = 0; nt < 4; nt++) {
            int gr = m0 + wm + mt * 16 + elr;
            int gc = n0 + wn + nt * 8 + elc;
            float* p0 = out + (size_t)gr * VOCAB + gc;
            float* p1 = out + (size_t)(gr + 8) * VOCAB + gc;
            if (full) {
                p0[0] = acc[mt][nt][0]; p0[1] = acc[mt][nt][1];
                p1[0] = acc[mt][nt][2]; p1[1] = acc[mt][nt][3];
            } else {
                if (gc < VOCAB)     { p0[0] = acc[mt][nt][0]; p1[0] = acc[mt][nt][2]; }
                if (gc + 1 < VOCAB) { p0[1] = acc[mt][nt][1]; p1[1] = acc[mt][nt][3]; }
            }
        }
    }
}

// ---------------------------------------------------------------------------
// Launch
// ---------------------------------------------------------------------------
extern "C" void kernel_launch(void* const* d_in, const int* in_sizes, int n_in,
                              void* d_out, int out_size)
{
    const int*   ids   = (const int*)  d_in[0];
    const float* embed = (const float*)d_in[1];
    const float* W_ih  = (const float*)d_in[2];
    const float* b_ih  = (const float*)d_in[3];
    const float* W_hh  = (const float*)d_in[4];
    const float* b_hh  = (const float*)d_in[5];
    const float* W_out = (const float*)d_in[6];
    float* out = (float*)d_out;

    float* gx_ptr;
    __nv_bfloat16 *a2_ptr, *b2_ptr;
    void* bar_ptr;
    cudaGetSymbolAddress((void**)&gx_ptr, g_gx);
    cudaGetSymbolAddress((void**)&a2_ptr, g_a2);
    cudaGetSymbolAddress((void**)&b2_ptr, g_b2);
    cudaGetSymbolAddress(&bar_ptr, g_bar);

    cudaFuncSetAttribute(lm_head_hmma,
                         cudaFuncAttributeMaxDynamicSharedMemorySize, LM_SMEM);

    // reset inter-CTA barrier for this launch (graph-capturable memset node)
    cudaMemsetAsync(bar_ptr, 0, sizeof(unsigned int));

    // 0) B2 = [hi | lo | hi] split of W_out
    {
        int nthreads = NPAD * 64;
        conv_w2<<<(nthreads + 255) / 256, 256>>>(W_out, b2_ptr);
    }

    // 1) gx = embed[ids] @ W_ih^T + b_ih
    {
        dim3 grid(GATES / 128, MTOK / 128);
        gemm_tn<true, true><<<grid, 256>>>(embed, ids, W_ih, b_ih,
                                           gx_ptr, MTOK, GATES, DMODEL);
    }

    // 2) multi-CTA GRU scan (emits A2 rows)
    gru_scan2<<<NC, GRU_THREADS>>>(gx_ptr, W_hh, b_hh, a2_ptr);

    // 3) LM head on HMMA tensor cores
    {
        dim3 grid(MTOK / 128, NPAD / 128);
        lm_head_hmma<<<grid, 256, LM_SMEM>>>(a2_ptr, b2_ptr, out);
    }
}